// round 3
// baseline (speedup 1.0000x reference)
#include <cuda_runtime.h>
#include <cstdint>

#define Bb 4
#define Nn 10000
#define Ee 160000
#define Mm 4
#define Hh 64
#define OUTd 64
#define Ff 64

#define ROWS (Bb*Nn*Mm)      /* 160000 projected rows, each 128 -> 64 */
#define EDGES (Bb*Ee)        /* 640000 */
#define NODES (Bb*Nn)        /* 40000 target buckets */

// Scratch (allocation-free rule: __device__ globals)
__device__ float g_nh[(size_t)ROWS * OUTd];   // 40.96 MB projected features
__device__ float g_coeff[EDGES];              // per-edge gate
__device__ int   g_count[NODES];              // histogram by (b,tgt)
__device__ int   g_off[NODES + 1];            // CSR offsets
__device__ int   g_pos[NODES];                // fill cursors
__device__ int   g_eid[EDGES];                // edge ids grouped by target

// ---------------------------------------------------------------------------
// Kernel 1: projection  nh_fts[row, o] = sum_c x[row,c] * W[c,o] + b[o]
// 64 rows/block, 256 threads, thread tile = 4 rows x 4 outs, float4 smem loads.
// ---------------------------------------------------------------------------
#define PROJ_ROWS_PER_BLK 64
#define XPITCH 132
#define PROJ_SMEM_BYTES ((128*64 + PROJ_ROWS_PER_BLK*XPITCH) * 4)

__global__ __launch_bounds__(256, 3)
void k_project(const float* __restrict__ node,
               const float* __restrict__ hidden,
               const float* __restrict__ Wnh,
               const float* __restrict__ bnh)
{
    extern __shared__ float sm[];
    float* Ws = sm;                  // [128][64]
    float* Xs = sm + 128 * 64;       // [64][XPITCH]

    const int tid  = threadIdx.x;
    const int row0 = blockIdx.x * PROJ_ROWS_PER_BLK;

    #pragma unroll
    for (int i = tid; i < 128 * 64; i += 256) Ws[i] = Wnh[i];

    #pragma unroll
    for (int i = tid; i < PROJ_ROWS_PER_BLK * 128; i += 256) {
        int r = i >> 7;
        int c = i & 127;
        int grow = row0 + r;
        float v = (c < 64) ? node[(size_t)grow * 64 + c]
                           : hidden[(size_t)grow * 64 + (c - 64)];
        Xs[r * XPITCH + c] = v;
    }
    __syncthreads();

    const int obase = (tid & 15) * 4;   // 16 col-groups * 4 = 64 outputs
    const int rbase = (tid >> 4) * 4;   // 16 row-groups * 4 = 64 rows

    float4 acc[4];
    {
        float4 b = *(const float4*)&bnh[obase];
        #pragma unroll
        for (int r = 0; r < 4; r++) acc[r] = b;
    }

    #pragma unroll 4
    for (int cb = 0; cb < 128; cb += 4) {
        const float4 w0 = *(const float4*)&Ws[(cb + 0) * 64 + obase];
        const float4 w1 = *(const float4*)&Ws[(cb + 1) * 64 + obase];
        const float4 w2 = *(const float4*)&Ws[(cb + 2) * 64 + obase];
        const float4 w3 = *(const float4*)&Ws[(cb + 3) * 64 + obase];
        #pragma unroll
        for (int r = 0; r < 4; r++) {
            const float4 x = *(const float4*)&Xs[(rbase + r) * XPITCH + cb];
            acc[r].x += x.x * w0.x; acc[r].y += x.x * w0.y; acc[r].z += x.x * w0.z; acc[r].w += x.x * w0.w;
            acc[r].x += x.y * w1.x; acc[r].y += x.y * w1.y; acc[r].z += x.y * w1.z; acc[r].w += x.y * w1.w;
            acc[r].x += x.z * w2.x; acc[r].y += x.z * w2.y; acc[r].z += x.z * w2.z; acc[r].w += x.z * w2.w;
            acc[r].x += x.w * w3.x; acc[r].y += x.w * w3.y; acc[r].z += x.w * w3.z; acc[r].w += x.w * w3.w;
        }
    }

    #pragma unroll
    for (int r = 0; r < 4; r++) {
        size_t off = (size_t)(row0 + rbase + r) * 64 + obase;
        *(float4*)&g_nh[off] = acc[r];
    }
}

// ---------------------------------------------------------------------------
// Kernel 0: zero the histogram
// ---------------------------------------------------------------------------
__global__ void k_zero()
{
    int i = blockIdx.x * blockDim.x + threadIdx.x;
    if (i < NODES) g_count[i] = 0;
}

// ---------------------------------------------------------------------------
// Kernel 2: per-edge gate + target histogram (fused).
// one warp per edge; lane 0 also bumps the CSR histogram.
// ---------------------------------------------------------------------------
__global__ __launch_bounds__(256)
void k_coeff_hist(const float* __restrict__ ef,
                  const float* __restrict__ We,
                  const float* __restrict__ be,
                  const int*   __restrict__ idx)
{
    int w    = (blockIdx.x * blockDim.x + threadIdx.x) >> 5;
    int lane = threadIdx.x & 31;
    if (w >= EDGES) return;

    const float* row = ef + (size_t)w * 64;
    float s = row[lane]      * __ldg(&We[lane])
            + row[lane + 32] * __ldg(&We[lane + 32]);

    #pragma unroll
    for (int off = 16; off > 0; off >>= 1)
        s += __shfl_xor_sync(0xFFFFFFFFu, s, off);

    if (lane == 0) {
        g_coeff[w] = s + __ldg(&be[0]);
        int b   = w / Ee;
        int tgt = idx[(size_t)w * 2 + 1];
        atomicAdd(&g_count[b * Nn + tgt], 1);
    }
}

// ---------------------------------------------------------------------------
// Kernel 3: single-block exclusive scan of 40000 counts -> g_off, g_pos
// ---------------------------------------------------------------------------
#define SCAN_T 1024
#define SCAN_CH 40           /* 1024*40 = 40960 >= NODES */

__global__ __launch_bounds__(SCAN_T)
void k_scan()
{
    __shared__ int part[SCAN_T];
    int t = threadIdx.x;
    int base = t * SCAN_CH;

    int s = 0;
    #pragma unroll 4
    for (int i = 0; i < SCAN_CH; i++) {
        int g = base + i;
        if (g < NODES) s += g_count[g];
    }
    part[t] = s;
    __syncthreads();

    // Hillis-Steele inclusive scan
    for (int off = 1; off < SCAN_T; off <<= 1) {
        int v = (t >= off) ? part[t - off] : 0;
        __syncthreads();
        part[t] += v;
        __syncthreads();
    }

    int run = part[t] - s;   // exclusive prefix for this chunk
    for (int i = 0; i < SCAN_CH; i++) {
        int g = base + i;
        if (g < NODES) {
            int c = g_count[g];
            g_off[g] = run;
            g_pos[g] = run;
            run += c;
        }
    }
    if (t == SCAN_T - 1) g_off[NODES] = EDGES;
}

// ---------------------------------------------------------------------------
// Kernel 4: fill CSR edge-id lists (order within bucket arbitrary)
// ---------------------------------------------------------------------------
__global__ __launch_bounds__(256)
void k_fill(const int* __restrict__ idx)
{
    int e = blockIdx.x * blockDim.x + threadIdx.x;
    if (e >= EDGES) return;
    int b   = e / Ee;
    int tgt = idx[(size_t)e * 2 + 1];
    int p = atomicAdd(&g_pos[b * Nn + tgt], 1);
    g_eid[p] = e;
}

// ---------------------------------------------------------------------------
// Kernel 5: accumulate. one warp per target node: gather src rows from L2,
// scale by coeff, sum in registers, one streaming store. No atomics.
// ---------------------------------------------------------------------------
__global__ __launch_bounds__(256)
void k_accum(const int* __restrict__ idx,
             float* __restrict__ out)
{
    int n    = (blockIdx.x * blockDim.x + threadIdx.x) >> 5;   // node bucket
    int lane = threadIdx.x & 31;
    if (n >= NODES) return;

    int beg = g_off[n];
    int end = g_off[n + 1];
    int b   = n / Nn;

    float4 a0 = make_float4(0.f, 0.f, 0.f, 0.f);
    float4 a1 = make_float4(0.f, 0.f, 0.f, 0.f);

    for (int j = beg; j < end; j++) {
        int   e   = g_eid[j];
        float cf  = __ldg(&g_coeff[e]);
        int   src = __ldg(&idx[(size_t)e * 2]);
        const float4* s4 = (const float4*)(g_nh + ((size_t)b * Nn + (size_t)src) * 256);
        float4 v0 = __ldg(&s4[lane]);
        float4 v1 = __ldg(&s4[lane + 32]);
        a0.x += cf * v0.x; a0.y += cf * v0.y; a0.z += cf * v0.z; a0.w += cf * v0.w;
        a1.x += cf * v1.x; a1.y += cf * v1.y; a1.z += cf * v1.z; a1.w += cf * v1.w;
    }

    float4* t4 = (float4*)(out + (size_t)n * 256);
    t4[lane]      = a0;
    t4[lane + 32] = a1;
}

// ---------------------------------------------------------------------------
// launch: zero -> project -> coeff+hist -> scan -> fill -> accum
// inputs: node_fts, hidden, edge_fts, W_nh, b_nh, W_e, b_e, edge_indices(i32)
// ---------------------------------------------------------------------------
extern "C" void kernel_launch(void* const* d_in, const int* in_sizes, int n_in,
                              void* d_out, int out_size)
{
    const float* node   = (const float*)d_in[0];
    const float* hidden = (const float*)d_in[1];
    const float* ef     = (const float*)d_in[2];
    const float* Wnh    = (const float*)d_in[3];
    const float* bnh    = (const float*)d_in[4];
    const float* We     = (const float*)d_in[5];
    const float* be     = (const float*)d_in[6];
    const int*   idx    = (const int*)d_in[7];
    float*       out    = (float*)d_out;

    cudaFuncSetAttribute(k_project, cudaFuncAttributeMaxDynamicSharedMemorySize,
                         PROJ_SMEM_BYTES);

    k_zero<<<(NODES + 255) / 256, 256>>>();
    k_project<<<ROWS / PROJ_ROWS_PER_BLK, 256, PROJ_SMEM_BYTES>>>(node, hidden, Wnh, bnh);
    k_coeff_hist<<<(EDGES + 7) / 8, 256>>>(ef, We, be, idx);
    k_scan<<<1, SCAN_T>>>();
    k_fill<<<(EDGES + 255) / 256, 256>>>(idx);
    k_accum<<<(NODES * 32 + 255) / 256, 256>>>(idx, out);
}

// round 4
// speedup vs baseline: 1.2391x; 1.2391x over previous
#include <cuda_runtime.h>
#include <cstdint>

#define Bb 4
#define Nn 10000
#define Ee 160000
#define Mm 4
#define Hh 64
#define OUTd 64
#define Ff 64

#define ROWS (Bb*Nn*Mm)      /* 160000 projected rows, each 128 -> 64 */
#define EDGES (Bb*Ee)        /* 640000 */
#define NODES (Bb*Nn)        /* 40000 target buckets */

// Scratch (allocation-free rule: __device__ globals)
__device__ float g_nh[(size_t)ROWS * OUTd];   // 40.96 MB projected features
__device__ float g_coeff[EDGES];              // per-edge gate
__device__ int   g_count[NODES];              // histogram by (b,tgt)
__device__ int   g_beg[NODES];                // segment start per node
__device__ int   g_pos[NODES];                // fill cursors
__device__ int   g_eid[EDGES];                // edge ids grouped by target
__device__ int   g_cursor;                    // segment allocator cursor

// ---------------------------------------------------------------------------
// Kernel 1: projection  nh_fts[row, o] = sum_c x[row,c] * W[c,o] + b[o]
// 64 rows/block, 256 threads, thread tile = 4 rows x 4 outs, float4 smem loads.
// ---------------------------------------------------------------------------
#define PROJ_ROWS_PER_BLK 64
#define XPITCH 132
#define PROJ_SMEM_BYTES ((128*64 + PROJ_ROWS_PER_BLK*XPITCH) * 4)

__global__ __launch_bounds__(256, 3)
void k_project(const float* __restrict__ node,
               const float* __restrict__ hidden,
               const float* __restrict__ Wnh,
               const float* __restrict__ bnh)
{
    extern __shared__ float sm[];
    float* Ws = sm;                  // [128][64]
    float* Xs = sm + 128 * 64;       // [64][XPITCH]

    const int tid  = threadIdx.x;
    const int row0 = blockIdx.x * PROJ_ROWS_PER_BLK;

    #pragma unroll
    for (int i = tid; i < 128 * 64; i += 256) Ws[i] = Wnh[i];

    #pragma unroll
    for (int i = tid; i < PROJ_ROWS_PER_BLK * 128; i += 256) {
        int r = i >> 7;
        int c = i & 127;
        int grow = row0 + r;
        float v = (c < 64) ? node[(size_t)grow * 64 + c]
                           : hidden[(size_t)grow * 64 + (c - 64)];
        Xs[r * XPITCH + c] = v;
    }
    __syncthreads();

    const int obase = (tid & 15) * 4;   // 16 col-groups * 4 = 64 outputs
    const int rbase = (tid >> 4) * 4;   // 16 row-groups * 4 = 64 rows

    float4 acc[4];
    {
        float4 b = *(const float4*)&bnh[obase];
        #pragma unroll
        for (int r = 0; r < 4; r++) acc[r] = b;
    }

    #pragma unroll 4
    for (int cb = 0; cb < 128; cb += 4) {
        const float4 w0 = *(const float4*)&Ws[(cb + 0) * 64 + obase];
        const float4 w1 = *(const float4*)&Ws[(cb + 1) * 64 + obase];
        const float4 w2 = *(const float4*)&Ws[(cb + 2) * 64 + obase];
        const float4 w3 = *(const float4*)&Ws[(cb + 3) * 64 + obase];
        #pragma unroll
        for (int r = 0; r < 4; r++) {
            const float4 x = *(const float4*)&Xs[(rbase + r) * XPITCH + cb];
            acc[r].x += x.x * w0.x; acc[r].y += x.x * w0.y; acc[r].z += x.x * w0.z; acc[r].w += x.x * w0.w;
            acc[r].x += x.y * w1.x; acc[r].y += x.y * w1.y; acc[r].z += x.y * w1.z; acc[r].w += x.y * w1.w;
            acc[r].x += x.z * w2.x; acc[r].y += x.z * w2.y; acc[r].z += x.z * w2.z; acc[r].w += x.z * w2.w;
            acc[r].x += x.w * w3.x; acc[r].y += x.w * w3.y; acc[r].z += x.w * w3.z; acc[r].w += x.w * w3.w;
        }
    }

    #pragma unroll
    for (int r = 0; r < 4; r++) {
        size_t off = (size_t)(row0 + rbase + r) * 64 + obase;
        *(float4*)&g_nh[off] = acc[r];
    }
}

// ---------------------------------------------------------------------------
// Kernel 0: zero histogram + allocator cursor
// ---------------------------------------------------------------------------
__global__ void k_zero()
{
    int i = blockIdx.x * blockDim.x + threadIdx.x;
    if (i < NODES) g_count[i] = 0;
    if (i == 0) g_cursor = 0;
}

// ---------------------------------------------------------------------------
// Kernel 2: per-edge gate + target histogram (fused).
// one warp per edge; lane 0 also bumps the CSR histogram.
// ---------------------------------------------------------------------------
__global__ __launch_bounds__(256)
void k_coeff_hist(const float* __restrict__ ef,
                  const float* __restrict__ We,
                  const float* __restrict__ be,
                  const int*   __restrict__ idx)
{
    int w    = (blockIdx.x * blockDim.x + threadIdx.x) >> 5;
    int lane = threadIdx.x & 31;
    if (w >= EDGES) return;

    const float* row = ef + (size_t)w * 64;
    float s = row[lane]      * __ldg(&We[lane])
            + row[lane + 32] * __ldg(&We[lane + 32]);

    #pragma unroll
    for (int off = 16; off > 0; off >>= 1)
        s += __shfl_xor_sync(0xFFFFFFFFu, s, off);

    if (lane == 0) {
        g_coeff[w] = s + __ldg(&be[0]);
        int b   = w / Ee;
        int tgt = idx[(size_t)w * 2 + 1];
        atomicAdd(&g_count[b * Nn + tgt], 1);
    }
}

// ---------------------------------------------------------------------------
// Kernel 3: warp-aggregated segment allocation (replaces global scan).
// Each thread owns one node; warp-scan counts; one atomicAdd per warp.
// Segment placement order is arbitrary; each node's segment is contiguous.
// ---------------------------------------------------------------------------
__global__ __launch_bounds__(256)
void k_alloc()
{
    int n    = blockIdx.x * blockDim.x + threadIdx.x;
    int lane = threadIdx.x & 31;

    int c = (n < NODES) ? g_count[n] : 0;

    // warp inclusive scan of c
    int s = c;
    #pragma unroll
    for (int off = 1; off < 32; off <<= 1) {
        int v = __shfl_up_sync(0xFFFFFFFFu, s, off);
        if (lane >= off) s += v;
    }
    int total = __shfl_sync(0xFFFFFFFFu, s, 31);

    int base = 0;
    if (lane == 31) base = atomicAdd(&g_cursor, total);
    base = __shfl_sync(0xFFFFFFFFu, base, 31);

    if (n < NODES) {
        int beg = base + s - c;   // exclusive prefix within warp
        g_beg[n] = beg;
        g_pos[n] = beg;
    }
}

// ---------------------------------------------------------------------------
// Kernel 4: fill edge-id lists (order within bucket arbitrary)
// ---------------------------------------------------------------------------
__global__ __launch_bounds__(256)
void k_fill(const int* __restrict__ idx)
{
    int e = blockIdx.x * blockDim.x + threadIdx.x;
    if (e >= EDGES) return;
    int b   = e / Ee;
    int tgt = idx[(size_t)e * 2 + 1];
    int p = atomicAdd(&g_pos[b * Nn + tgt], 1);
    g_eid[p] = e;
}

// ---------------------------------------------------------------------------
// Kernel 5: accumulate. one warp per target node: gather src rows from L2,
// scale by coeff, sum in registers, one streaming store. No atomics.
// ---------------------------------------------------------------------------
__global__ __launch_bounds__(256)
void k_accum(const int* __restrict__ idx,
             float* __restrict__ out)
{
    int n    = (blockIdx.x * blockDim.x + threadIdx.x) >> 5;   // node bucket
    int lane = threadIdx.x & 31;
    if (n >= NODES) return;

    int beg = g_beg[n];
    int end = beg + g_count[n];
    int b   = n / Nn;

    float4 a0 = make_float4(0.f, 0.f, 0.f, 0.f);
    float4 a1 = make_float4(0.f, 0.f, 0.f, 0.f);

    for (int j = beg; j < end; j++) {
        int   e   = g_eid[j];
        float cf  = __ldg(&g_coeff[e]);
        int   src = __ldg(&idx[(size_t)e * 2]);
        const float4* s4 = (const float4*)(g_nh + ((size_t)b * Nn + (size_t)src) * 256);
        float4 v0 = __ldg(&s4[lane]);
        float4 v1 = __ldg(&s4[lane + 32]);
        a0.x += cf * v0.x; a0.y += cf * v0.y; a0.z += cf * v0.z; a0.w += cf * v0.w;
        a1.x += cf * v1.x; a1.y += cf * v1.y; a1.z += cf * v1.z; a1.w += cf * v1.w;
    }

    float4* t4 = (float4*)(out + (size_t)n * 256);
    t4[lane]      = a0;
    t4[lane + 32] = a1;
}

// ---------------------------------------------------------------------------
// launch: zero -> project -> coeff+hist -> alloc -> fill -> accum
// inputs: node_fts, hidden, edge_fts, W_nh, b_nh, W_e, b_e, edge_indices(i32)
// ---------------------------------------------------------------------------
extern "C" void kernel_launch(void* const* d_in, const int* in_sizes, int n_in,
                              void* d_out, int out_size)
{
    const float* node   = (const float*)d_in[0];
    const float* hidden = (const float*)d_in[1];
    const float* ef     = (const float*)d_in[2];
    const float* Wnh    = (const float*)d_in[3];
    const float* bnh    = (const float*)d_in[4];
    const float* We     = (const float*)d_in[5];
    const float* be     = (const float*)d_in[6];
    const int*   idx    = (const int*)d_in[7];
    float*       out    = (float*)d_out;

    cudaFuncSetAttribute(k_project, cudaFuncAttributeMaxDynamicSharedMemorySize,
                         PROJ_SMEM_BYTES);

    k_zero<<<(NODES + 255) / 256, 256>>>();
    k_project<<<ROWS / PROJ_ROWS_PER_BLK, 256, PROJ_SMEM_BYTES>>>(node, hidden, Wnh, bnh);
    k_coeff_hist<<<(EDGES + 7) / 8, 256>>>(ef, We, be, idx);
    k_alloc<<<(NODES + 255) / 256, 256>>>();
    k_fill<<<(EDGES + 255) / 256, 256>>>(idx);
    k_accum<<<(NODES * 32 + 255) / 256, 256>>>(idx, out);
}